// round 1
// baseline (speedup 1.0000x reference)
#include <cuda_runtime.h>
#include <math.h>
#include <stdint.h>

#define NROWS 16384
#define DIM   128
#define KTOP  5
#define BM    64
#define BN    64

// ---------------- device scratch (no allocations allowed) ----------------
__device__ float g_x[NROWS * DIM];        // row-normalized z (8 MB)
__device__ int   g_topk[NROWS * KTOP];    // top-5 indices per row
__device__ float g_rowterm[NROWS];        // per-row loss term

// ---------------- kernel 1: row L2-normalize ----------------
__global__ void normalize_kernel(const float* __restrict__ z) {
    int row = blockIdx.x * blockDim.y + threadIdx.y;   // 8 rows / block
    int l = threadIdx.x;                                // 32 lanes
    const float* zr = z + (size_t)row * DIM;
    float v0 = zr[l], v1 = zr[l + 32], v2 = zr[l + 64], v3 = zr[l + 96];
    float ss = v0 * v0 + v1 * v1 + v2 * v2 + v3 * v3;
    #pragma unroll
    for (int o = 16; o > 0; o >>= 1) ss += __shfl_xor_sync(0xffffffffu, ss, o);
    float inv = 1.0f / fmaxf(sqrtf(ss), 1e-12f);
    float* xr = g_x + (size_t)row * DIM;
    xr[l] = v0 * inv; xr[l + 32] = v1 * inv; xr[l + 64] = v2 * inv; xr[l + 96] = v3 * inv;
}

// ---------------- fused GEMM (x x^T) + per-row top-5 ----------------
// SMEM tile layout: logical (r in [0,64), k in [0,128)) stored at word
//   r*128 + 4*((k>>2) ^ (r>>2)) + (k&3)
// -> float4 stores along k and float4 frag loads are conflict-free.

__device__ __forceinline__ void load_tile_T(float* T, const float* __restrict__ src, int tid) {
    int w = tid >> 5, q = tid & 31;                 // warp, lane = k-granule
    #pragma unroll
    for (int p = 0; p < 8; p++) {
        int r = p * 8 + w;
        float4 v = *(const float4*)(src + (size_t)r * DIM + 4 * q);
        *(float4*)(T + r * 128 + 4 * (q ^ (r >> 2))) = v;
    }
}

#define DOT4(c, A, B) \
    c = fmaf((A).x, (B).x, fmaf((A).y, (B).y, fmaf((A).z, (B).z, fmaf((A).w, (B).w, (c)))))

__global__ __launch_bounds__(256, 2) void gemm_topk_kernel() {
    extern __shared__ float smem[];
    float* As = smem;            // 64*128 floats = 32 KB
    float* Bs = smem + BM * DIM; // 32 KB
    int tid = threadIdx.x;
    int tx = tid & 15, ty = tid >> 4;
    int R0 = blockIdx.x * BM;

    load_tile_T(As, g_x + (size_t)R0 * DIM, tid);

    // per-thread top-5 for its 4 rows, sorted descending
    float tv0[KTOP], tv1[KTOP], tv2[KTOP], tv3[KTOP];
    int   ti0[KTOP], ti1[KTOP], ti2[KTOP], ti3[KTOP];
    #pragma unroll
    for (int p = 0; p < KTOP; p++) {
        tv0[p] = tv1[p] = tv2[p] = tv3[p] = -INFINITY;
        ti0[p] = ti1[p] = ti2[p] = ti3[p] = 0x7fffffff;
    }

    const float* Ar0 = As + (4 * ty + 0) * 128;
    const float* Ar1 = As + (4 * ty + 1) * 128;
    const float* Ar2 = As + (4 * ty + 2) * 128;
    const float* Ar3 = As + (4 * ty + 3) * 128;
    const float* Br0 = Bs + (4 * tx + 0) * 128;
    const float* Br1 = Bs + (4 * tx + 1) * 128;
    const float* Br2 = Bs + (4 * tx + 2) * 128;
    const float* Br3 = Bs + (4 * tx + 3) * 128;

    for (int c0 = 0; c0 < NROWS; c0 += BN) {
        __syncthreads();
        load_tile_T(Bs, g_x + (size_t)c0 * DIM, tid);
        __syncthreads();

        float a00 = 0.f, a01 = 0.f, a02 = 0.f, a03 = 0.f;
        float a10 = 0.f, a11 = 0.f, a12 = 0.f, a13 = 0.f;
        float a20 = 0.f, a21 = 0.f, a22 = 0.f, a23 = 0.f;
        float a30 = 0.f, a31 = 0.f, a32 = 0.f, a33 = 0.f;

        #pragma unroll 4
        for (int kc = 0; kc < 32; kc++) {
            int oa = 4 * (kc ^ ty);
            int ob = 4 * (kc ^ tx);
            float4 fa0 = *(const float4*)(Ar0 + oa);
            float4 fa1 = *(const float4*)(Ar1 + oa);
            float4 fa2 = *(const float4*)(Ar2 + oa);
            float4 fa3 = *(const float4*)(Ar3 + oa);
            float4 fb0 = *(const float4*)(Br0 + ob);
            float4 fb1 = *(const float4*)(Br1 + ob);
            float4 fb2 = *(const float4*)(Br2 + ob);
            float4 fb3 = *(const float4*)(Br3 + ob);
            DOT4(a00, fa0, fb0); DOT4(a01, fa0, fb1); DOT4(a02, fa0, fb2); DOT4(a03, fa0, fb3);
            DOT4(a10, fa1, fb0); DOT4(a11, fa1, fb1); DOT4(a12, fa1, fb2); DOT4(a13, fa1, fb3);
            DOT4(a20, fa2, fb0); DOT4(a21, fa2, fb1); DOT4(a22, fa2, fb2); DOT4(a23, fa2, fb3);
            DOT4(a30, fa3, fb0); DOT4(a31, fa3, fb1); DOT4(a32, fa3, fb2); DOT4(a33, fa3, fb3);
        }

        // top-5 insert: strictly-greater keeps earliest (lowest) index on ties
        #define TK_INS(TV, TI, VAL, COL)                                            \
            do { float _v = (VAL);                                                  \
                if (_v > TV[KTOP - 1]) {                                            \
                    TV[KTOP - 1] = _v; TI[KTOP - 1] = (COL);                        \
                    _Pragma("unroll")                                               \
                    for (int _p = KTOP - 1; _p > 0; _p--) {                         \
                        if (TV[_p] > TV[_p - 1]) {                                  \
                            float _tf = TV[_p]; TV[_p] = TV[_p - 1]; TV[_p - 1] = _tf; \
                            int _tn = TI[_p]; TI[_p] = TI[_p - 1]; TI[_p - 1] = _tn;   \
                        }                                                           \
                    }                                                               \
                }                                                                   \
            } while (0)

        int cb = c0 + 4 * tx;
        TK_INS(tv0, ti0, a00, cb + 0); TK_INS(tv0, ti0, a01, cb + 1);
        TK_INS(tv0, ti0, a02, cb + 2); TK_INS(tv0, ti0, a03, cb + 3);
        TK_INS(tv1, ti1, a10, cb + 0); TK_INS(tv1, ti1, a11, cb + 1);
        TK_INS(tv1, ti1, a12, cb + 2); TK_INS(tv1, ti1, a13, cb + 3);
        TK_INS(tv2, ti2, a20, cb + 0); TK_INS(tv2, ti2, a21, cb + 1);
        TK_INS(tv2, ti2, a22, cb + 2); TK_INS(tv2, ti2, a23, cb + 3);
        TK_INS(tv3, ti3, a30, cb + 0); TK_INS(tv3, ti3, a31, cb + 1);
        TK_INS(tv3, ti3, a32, cb + 2); TK_INS(tv3, ti3, a33, cb + 3);
    }

    // ---- merge 16 thread-local top-5 lists per row (global tie: lower index) ----
    __syncthreads();
    float* mv = smem;                   // 64 rows * 80 cands
    int*   mi = (int*)(smem + BM * 80); // after 5120 floats
    #pragma unroll
    for (int p = 0; p < KTOP; p++) {
        mv[(4 * ty + 0) * 80 + tx * KTOP + p] = tv0[p];
        mv[(4 * ty + 1) * 80 + tx * KTOP + p] = tv1[p];
        mv[(4 * ty + 2) * 80 + tx * KTOP + p] = tv2[p];
        mv[(4 * ty + 3) * 80 + tx * KTOP + p] = tv3[p];
        mi[(4 * ty + 0) * 80 + tx * KTOP + p] = ti0[p];
        mi[(4 * ty + 1) * 80 + tx * KTOP + p] = ti1[p];
        mi[(4 * ty + 2) * 80 + tx * KTOP + p] = ti2[p];
        mi[(4 * ty + 3) * 80 + tx * KTOP + p] = ti3[p];
    }
    __syncthreads();
    if (tid < BM) {
        float* rv = mv + tid * 80;
        int*   ri = mi + tid * 80;
        for (int r = 0; r < KTOP; r++) {
            float bv = -INFINITY; int bi = 0x7fffffff; int bs = 0;
            for (int s = 0; s < 80; s++) {
                float v = rv[s]; int id = ri[s];
                if (v > bv || (v == bv && id < bi)) { bv = v; bi = id; bs = s; }
            }
            rv[bs] = -INFINITY;
            g_topk[(size_t)(R0 + tid) * KTOP + r] = bi;
        }
    }
}

// ---------------- kernel 3: per-row loss term ----------------
__device__ __forceinline__ float sigmoid_stable(float x) {
    if (x >= 0.f) { return 1.f / (1.f + expf(-x)); }
    float e = expf(x); return e / (1.f + e);
}

__global__ void loss_kernel(const float* __restrict__ z, const int* __restrict__ nl32) {
    int warp = threadIdx.x >> 5;
    int row  = blockIdx.x * 8 + warp;
    int l    = threadIdx.x & 31;

    // dtype probe: int64 permutation => all high words zero; int32 permutation
    // has at most one zero among elements 1,3,5,7.
    bool is64 = ((nl32[1] | nl32[3] | nl32[5] | nl32[7]) == 0);
    long long nidx = is64 ? ((const long long*)nl32)[row] : (long long)nl32[row];

    const float* zr = z + (size_t)row * DIM;
    const float* zn = z + (size_t)nidx * DIM;
    const float* p0 = z + (size_t)g_topk[row * KTOP + 0] * DIM;
    const float* p1 = z + (size_t)g_topk[row * KTOP + 1] * DIM;
    const float* p2 = z + (size_t)g_topk[row * KTOP + 2] * DIM;
    const float* p3 = z + (size_t)g_topk[row * KTOP + 3] * DIM;
    const float* p4 = z + (size_t)g_topk[row * KTOP + 4] * DIM;

    float pacc = 0.f, nacc = 0.f;
    #pragma unroll
    for (int c = 0; c < 4; c++) {
        int d = l + 32 * c;
        float zi = zr[d];
        float m = (p0[d] + p1[d] + p2[d] + p3[d] + p4[d]) * (1.0f / 5.0f);
        pacc = fmaf(m, zi, pacc);
        nacc = fmaf(zn[d], zi, nacc);
    }
    #pragma unroll
    for (int o = 16; o > 0; o >>= 1) {
        pacc += __shfl_xor_sync(0xffffffffu, pacc, o);
        nacc += __shfl_xor_sync(0xffffffffu, nacc, o);
    }
    if (l == 0) {
        float sp = sigmoid_stable(pacc);   // mu = 1
        float sn = sigmoid_stable(nacc);
        g_rowterm[row] = -(logf(sp + 1e-15f) + logf((1.0f - sn) + 1e-15f));
    }
}

// ---------------- kernel 4: deterministic reduction ----------------
__global__ void reduce_kernel(float* __restrict__ out) {
    __shared__ float sh[256];
    float s = 0.f;
    for (int i = threadIdx.x; i < NROWS; i += 256) s += g_rowterm[i];
    sh[threadIdx.x] = s;
    __syncthreads();
    #pragma unroll
    for (int o = 128; o > 0; o >>= 1) {
        if (threadIdx.x < o) sh[threadIdx.x] += sh[threadIdx.x + o];
        __syncthreads();
    }
    if (threadIdx.x == 0) out[0] = sh[0] * (1.0f / NROWS);
}

// ---------------- launch ----------------
extern "C" void kernel_launch(void* const* d_in, const int* in_sizes, int n_in,
                              void* d_out, int out_size) {
    const float* z; const int* nl;
    if (in_sizes[0] == NROWS * DIM) { z = (const float*)d_in[0]; nl = (const int*)d_in[1]; }
    else                            { z = (const float*)d_in[1]; nl = (const int*)d_in[0]; }

    cudaFuncSetAttribute(gemm_topk_kernel,
                         cudaFuncAttributeMaxDynamicSharedMemorySize, 65536);

    normalize_kernel<<<NROWS / 8, dim3(32, 8)>>>(z);
    gemm_topk_kernel<<<NROWS / BM, 256, 65536>>>();
    loss_kernel<<<NROWS / 8, 256>>>(z, nl);
    reduce_kernel<<<1, 256>>>((float*)d_out);
}

// round 2
// speedup vs baseline: 4.6126x; 4.6126x over previous
#include <cuda_runtime.h>
#include <cuda_bf16.h>
#include <math.h>
#include <stdint.h>

#define NROWS 16384
#define DIM   128
#define KTOP  5
#define BM    128
#define BN    128
#define NCHUNK (NROWS / BN)
#define GTHREADS 512
#define MSTRIDE 85   // merge smem stride, coprime with 32 -> conflict-free

// ---------------- device scratch (no allocations allowed) ----------------
__device__ __nv_bfloat16 g_xb[NROWS * DIM];   // row-normalized z, bf16 (4 MB)
__device__ int   g_topk[NROWS * KTOP];
__device__ float g_rowterm[NROWS];

// ---------------- kernel 1: row L2-normalize -> bf16 ----------------
__global__ void normalize_kernel(const float* __restrict__ z) {
    int row = blockIdx.x * blockDim.y + threadIdx.y;   // 8 rows / block
    int l = threadIdx.x;                                // 32 lanes
    float4 v = ((const float4*)(z + (size_t)row * DIM))[l];
    float ss = v.x * v.x + v.y * v.y + v.z * v.z + v.w * v.w;
    #pragma unroll
    for (int o = 16; o > 0; o >>= 1) ss += __shfl_xor_sync(0xffffffffu, ss, o);
    float inv = 1.0f / fmaxf(sqrtf(ss), 1e-12f);
    __nv_bfloat162* out = (__nv_bfloat162*)(g_xb + (size_t)row * DIM);
    out[2 * l + 0] = __floats2bfloat162_rn(v.x * inv, v.y * inv);
    out[2 * l + 1] = __floats2bfloat162_rn(v.z * inv, v.w * inv);
}

// ---------------- PTX helpers ----------------
__device__ __forceinline__ void ldsm_x4(uint32_t* r, uint32_t addr) {
    asm volatile("ldmatrix.sync.aligned.m8n8.x4.shared.b16 {%0,%1,%2,%3}, [%4];"
                 : "=r"(r[0]), "=r"(r[1]), "=r"(r[2]), "=r"(r[3]) : "r"(addr));
}
__device__ __forceinline__ void mma16816(float* c, const uint32_t* a, uint32_t b0, uint32_t b1) {
    asm volatile(
        "mma.sync.aligned.m16n8k16.row.col.f32.bf16.bf16.f32 "
        "{%0,%1,%2,%3}, {%4,%5,%6,%7}, {%8,%9}, {%0,%1,%2,%3};"
        : "+f"(c[0]), "+f"(c[1]), "+f"(c[2]), "+f"(c[3])
        : "r"(a[0]), "r"(a[1]), "r"(a[2]), "r"(a[3]), "r"(b0), "r"(b1));
}
// 128 rows x 16 granules of 16B, XOR-swizzled
__device__ __forceinline__ void cp_tile(uint4* sdst, const uint4* gsrc, int tid) {
    #pragma unroll
    for (int i = 0; i < 4; i++) {
        int idx = tid + i * GTHREADS;            // 0..2047
        int row = idx >> 4, g = idx & 15;
        uint32_t d = (uint32_t)__cvta_generic_to_shared(sdst + row * 16 + (g ^ (row & 7)));
        asm volatile("cp.async.cg.shared.global [%0], [%1], 16;"
                     :: "r"(d), "l"(gsrc + row * 16 + g) : "memory");
    }
}

// ---------------- fused bf16 MMA GEMM + per-row top-5 ----------------
__global__ __launch_bounds__(GTHREADS, 1) void gemm_topk_kernel() {
    extern __shared__ uint4 smem[];
    uint4* As  = smem;                 // 2048 uint4 = 32 KB
    uint4* Bs0 = smem + 2048;
    uint4* Bs1 = smem + 4096;
    int tid  = threadIdx.x;
    int lane = tid & 31, wid = tid >> 5;
    int wm = wid >> 2, wn = wid & 3;   // 4x4 warp grid
    int R0 = blockIdx.x * BM;
    const uint4* X = (const uint4*)g_xb;   // [NROWS][16]

    cp_tile(As, X + (size_t)R0 * 16, tid);
    cp_tile(Bs0, X, tid);
    asm volatile("cp.async.commit_group;" ::: "memory");

    uint32_t sA  = (uint32_t)__cvta_generic_to_shared(As);
    uint32_t sB0 = (uint32_t)__cvta_generic_to_shared(Bs0);
    uint32_t sB1 = (uint32_t)__cvta_generic_to_shared(Bs1);

    // per-thread top-5 for 4 owned rows (sorted desc), threshold = 5th value
    float lv[4][KTOP]; int li[4][KTOP]; float thr[4];
    #pragma unroll
    for (int r = 0; r < 4; r++) {
        thr[r] = -INFINITY;
        #pragma unroll
        for (int p = 0; p < KTOP; p++) { lv[r][p] = -INFINITY; li[r][p] = 0x7fffffff; }
    }

    for (int c = 0; c < NCHUNK; c++) {
        if (c + 1 < NCHUNK)
            cp_tile((c & 1) ? Bs0 : Bs1, X + (size_t)(c + 1) * BN * 16, tid);
        asm volatile("cp.async.commit_group;" ::: "memory");
        asm volatile("cp.async.wait_group 1;" ::: "memory");
        __syncthreads();

        uint32_t sB = (c & 1) ? sB1 : sB0;
        float acc[2][4][4];
        #pragma unroll
        for (int mt = 0; mt < 2; mt++)
            #pragma unroll
            for (int nt = 0; nt < 4; nt++)
                #pragma unroll
                for (int j = 0; j < 4; j++) acc[mt][nt][j] = 0.f;

        #pragma unroll
        for (int ks = 0; ks < 8; ks++) {
            uint32_t a[2][4], b[2][4];
            #pragma unroll
            for (int mt = 0; mt < 2; mt++) {
                int row = wm * 32 + mt * 16 + (lane & 15);
                int g = 2 * ks + (lane >> 4);
                ldsm_x4(a[mt], sA + (uint32_t)(row * 16 + (g ^ (row & 7))) * 16u);
            }
            #pragma unroll
            for (int nn = 0; nn < 2; nn++) {
                int row = wn * 32 + nn * 16 + (lane & 15);
                int g = 2 * ks + (lane >> 4);
                ldsm_x4(b[nn], sB + (uint32_t)(row * 16 + (g ^ (row & 7))) * 16u);
            }
            #pragma unroll
            for (int mt = 0; mt < 2; mt++)
                #pragma unroll
                for (int nt = 0; nt < 4; nt++)
                    mma16816(acc[mt][nt], a[mt], b[nt >> 1][nt & 1], b[nt >> 1][(nt & 1) + 2]);
        }

        // top-5 update (registers only; insert path is rare)
        #pragma unroll
        for (int mt = 0; mt < 2; mt++)
            #pragma unroll
            for (int h = 0; h < 2; h++) {
                const int r = mt * 2 + h;
                #pragma unroll
                for (int nt = 0; nt < 4; nt++)
                    #pragma unroll
                    for (int q = 0; q < 2; q++) {
                        float v = acc[mt][nt][2 * h + q];
                        if (v > thr[r]) {
                            int col = c * BN + wn * 32 + nt * 8 + 2 * (lane & 3) + q;
                            lv[r][KTOP - 1] = v; li[r][KTOP - 1] = col;
                            #pragma unroll
                            for (int p = KTOP - 1; p > 0; p--) {
                                if (lv[r][p] > lv[r][p - 1]) {
                                    float tf = lv[r][p]; lv[r][p] = lv[r][p - 1]; lv[r][p - 1] = tf;
                                    int tn = li[r][p]; li[r][p] = li[r][p - 1]; li[r][p - 1] = tn;
                                }
                            }
                            thr[r] = lv[r][KTOP - 1];
                        }
                    }
            }
        __syncthreads();   // all warps done reading this B buffer before next prefetch overwrites
    }

    // ---- merge: 16 lane-lists per row, tie-break (value desc, index asc) ----
    float* mv = (float*)smem;                     // 128 * MSTRIDE floats
    int*   mi = (int*)smem + BM * MSTRIDE;
    #pragma unroll
    for (int r = 0; r < 4; r++) {
        int row_local = wm * 32 + (r >> 1) * 16 + (r & 1) * 8 + (lane >> 2);
        int slot = wn * 4 + (lane & 3);
        #pragma unroll
        for (int p = 0; p < KTOP; p++) {
            mv[row_local * MSTRIDE + slot * KTOP + p] = lv[r][p];
            mi[row_local * MSTRIDE + slot * KTOP + p] = li[r][p];
        }
    }
    __syncthreads();
    if (tid < BM) {
        float* rv = mv + tid * MSTRIDE;
        int*   ri = mi + tid * MSTRIDE;
        #pragma unroll
        for (int r = 0; r < KTOP; r++) {
            float bv = -INFINITY; int bi = 0x7fffffff; int bs = 0;
            for (int s = 0; s < 80; s++) {
                float v = rv[s]; int id = ri[s];
                if (v > bv || (v == bv && id < bi)) { bv = v; bi = id; bs = s; }
            }
            rv[bs] = -INFINITY;
            g_topk[(size_t)(R0 + tid) * KTOP + r] = bi;
        }
    }
}

// ---------------- kernel 3: per-row loss term (exact fp32) ----------------
__device__ __forceinline__ float sigmoid_stable(float x) {
    if (x >= 0.f) { return 1.f / (1.f + expf(-x)); }
    float e = expf(x); return e / (1.f + e);
}

__global__ void loss_kernel(const float* __restrict__ z, const int* __restrict__ nl32) {
    int warp = threadIdx.x >> 5;
    int row  = blockIdx.x * 8 + warp;
    int l    = threadIdx.x & 31;

    bool is64 = ((nl32[1] | nl32[3] | nl32[5] | nl32[7]) == 0);
    long long nidx = is64 ? ((const long long*)nl32)[row] : (long long)nl32[row];

    const float* zr = z + (size_t)row * DIM;
    const float* zn = z + (size_t)nidx * DIM;
    const float* p0 = z + (size_t)g_topk[row * KTOP + 0] * DIM;
    const float* p1 = z + (size_t)g_topk[row * KTOP + 1] * DIM;
    const float* p2 = z + (size_t)g_topk[row * KTOP + 2] * DIM;
    const float* p3 = z + (size_t)g_topk[row * KTOP + 3] * DIM;
    const float* p4 = z + (size_t)g_topk[row * KTOP + 4] * DIM;

    float pacc = 0.f, nacc = 0.f;
    #pragma unroll
    for (int c = 0; c < 4; c++) {
        int d = l + 32 * c;
        float zi = zr[d];
        float m = (p0[d] + p1[d] + p2[d] + p3[d] + p4[d]) * (1.0f / 5.0f);
        pacc = fmaf(m, zi, pacc);
        nacc = fmaf(zn[d], zi, nacc);
    }
    #pragma unroll
    for (int o = 16; o > 0; o >>= 1) {
        pacc += __shfl_xor_sync(0xffffffffu, pacc, o);
        nacc += __shfl_xor_sync(0xffffffffu, nacc, o);
    }
    if (l == 0) {
        float sp = sigmoid_stable(pacc);
        float sn = sigmoid_stable(nacc);
        g_rowterm[row] = -(logf(sp + 1e-15f) + logf((1.0f - sn) + 1e-15f));
    }
}

// ---------------- kernel 4: deterministic reduction ----------------
__global__ void reduce_kernel(float* __restrict__ out) {
    __shared__ float sh[256];
    float s = 0.f;
    for (int i = threadIdx.x; i < NROWS; i += 256) s += g_rowterm[i];
    sh[threadIdx.x] = s;
    __syncthreads();
    #pragma unroll
    for (int o = 128; o > 0; o >>= 1) {
        if (threadIdx.x < o) sh[threadIdx.x] += sh[threadIdx.x + o];
        __syncthreads();
    }
    if (threadIdx.x == 0) out[0] = sh[0] * (1.0f / NROWS);
}

// ---------------- launch ----------------
extern "C" void kernel_launch(void* const* d_in, const int* in_sizes, int n_in,
                              void* d_out, int out_size) {
    const float* z; const int* nl;
    if (in_sizes[0] == NROWS * DIM) { z = (const float*)d_in[0]; nl = (const int*)d_in[1]; }
    else                            { z = (const float*)d_in[1]; nl = (const int*)d_in[0]; }

    cudaFuncSetAttribute(gemm_topk_kernel,
                         cudaFuncAttributeMaxDynamicSharedMemorySize, 98304);

    normalize_kernel<<<NROWS / 8, dim3(32, 8)>>>(z);
    gemm_topk_kernel<<<NROWS / BM, GTHREADS, 98304>>>();
    loss_kernel<<<NROWS / 8, 256>>>(z, nl);
    reduce_kernel<<<1, 256>>>((float*)d_out);
}